// round 9
// baseline (speedup 1.0000x reference)
#include <cuda_runtime.h>
#include <cuda_fp16.h>
#include <cstdint>

// Problem constants (TMDLayer): B=8, N=2048, F=256, L=16, EPS=0.25
#define BB 8
#define NN 2048
#define FF 256
#define LL 16
#define EPSV 0.25f
#define MTILES 32
#define TK 64
#define NT 16
#define NPAIRS 136
#define NL2E 1.4426950408889634f

typedef unsigned long long ull;

// ---------------- device scratch ----------------
__device__ __half g_zh[BB * NN * LL];
__device__ float g_sqh[BB * NN];
__device__ float g_pi[BB * NN];
__device__ float g_c[BB * NN];
__device__ float g_qpart[(size_t)BB * NT * NN];
__device__ __align__(128) __half g_K[(size_t)BB * NN * NN];   // [b][n][m]
__device__ __align__(128) __half g_y[(size_t)BB * FF * NN];   // [b][f][m]

// ---------------- helpers ----------------
__device__ __forceinline__ unsigned smem_u32(const void* p) {
    unsigned a;
    asm("{ .reg .u64 t; cvta.to.shared.u64 t, %1; cvt.u32.u64 %0, t; }" : "=r"(a) : "l"(p));
    return a;
}
__device__ __forceinline__ void cp_async16s(unsigned dst, const void* src) {
    asm volatile("cp.async.cg.shared.global [%0], [%1], 16;\n" :: "r"(dst), "l"(src));
}
__device__ __forceinline__ void cp_commit() { asm volatile("cp.async.commit_group;\n"); }
__device__ __forceinline__ void cp_wait0() { asm volatile("cp.async.wait_group 0;\n"); }
__device__ __forceinline__ void cp_wait1() { asm volatile("cp.async.wait_group 1;\n"); }
__device__ __forceinline__ void cp_wait2() { asm volatile("cp.async.wait_group 2;\n"); }

__device__ __forceinline__ ull ffma2(ull a, ull b, ull c) {
    ull d;
    asm("fma.rn.f32x2 %0, %1, %2, %3;" : "=l"(d) : "l"(a), "l"(b), "l"(c));
    return d;
}
union F2U { ull u; float2 f; };
__device__ __forceinline__ float hadd2(ull v) { F2U t; t.u = v; return t.f.x + t.f.y; }

__device__ __forceinline__ void mma16816(float* d, const uint32_t* a, const uint32_t* b) {
    asm volatile(
        "mma.sync.aligned.m16n8k16.row.col.f32.f16.f16.f32 "
        "{%0,%1,%2,%3}, {%4,%5,%6,%7}, {%8,%9}, {%0,%1,%2,%3};"
        : "+f"(d[0]), "+f"(d[1]), "+f"(d[2]), "+f"(d[3])
        : "r"(a[0]), "r"(a[1]), "r"(a[2]), "r"(a[3]), "r"(b[0]), "r"(b[1]));
}
__device__ __forceinline__ void ldsm4(uint32_t* r, unsigned addr) {
    asm volatile("ldmatrix.sync.aligned.m8n8.x4.shared.b16 {%0,%1,%2,%3}, [%4];"
        : "=r"(r[0]), "=r"(r[1]), "=r"(r[2]), "=r"(r[3]) : "r"(addr));
}
__device__ __forceinline__ uint32_t ex2_f16x2(uint32_t a) {
    uint32_t d;
    asm("ex2.approx.f16x2 %0, %1;" : "=r"(d) : "r"(a));
    return d;
}
__device__ __forceinline__ uint32_t movmat_t(uint32_t a) {
    uint32_t d;
    asm("movmatrix.sync.aligned.m8n8.trans.b16 %0, %1;" : "=r"(d) : "r"(a));
    return d;
}
__device__ __forceinline__ float h2sum(uint32_t h) {
    __half2 v = *reinterpret_cast<__half2*>(&h);
    float2 f = __half22float2(v);
    return f.x + f.y;
}

// =====================================================================
// Kernel 1 (fused): z, zh, sqh, pi.  proj dot with 4-way split accum.
// =====================================================================
__global__ void __launch_bounds__(256) k_zpi(const float* __restrict__ x,
                                             const float* __restrict__ pw,
                                             const float* __restrict__ pb,
                                             const float* __restrict__ w1,
                                             const float* __restrict__ b1,
                                             const float* __restrict__ w2,
                                             const float* __restrict__ b2) {
    __shared__ __align__(16) float xs[16][260];
    __shared__ __align__(16) float pws[16][258];
    __shared__ __align__(16) float zs[16][18];
    __shared__ float red[16][17];
    __shared__ __align__(16) float w1s[256][18];
    __shared__ float b1s[256];
    __shared__ float w2s[256];

    const int tid = threadIdx.x;
    const int p0 = blockIdx.x * 16;
    const float* xbase = x + (size_t)p0 * FF;

    for (int i = tid; i < 16 * 64; i += 256) {
        int r = i >> 6, c = (i & 63) << 2;
        float4 v = *reinterpret_cast<const float4*>(xbase + r * FF + c);
        *reinterpret_cast<float4*>(&xs[r][c]) = v;
    }
    for (int i = tid; i < LL * FF; i += 256) pws[i >> 8][i & 255] = pw[i];
    for (int i = tid; i < FF * LL; i += 256) w1s[i >> 4][i & 15] = w1[i];
    b1s[tid] = b1[tid];
    w2s[tid] = w2[tid];
    __syncthreads();

    const int n = tid >> 4;
    const int l = tid & 15;
    ull a0 = 0ULL, a1 = 0ULL, a2 = 0ULL, a3 = 0ULL;   // 4-way ILP
#pragma unroll 8
    for (int f8 = 0; f8 < FF / 8; f8++) {
        const int base = f8 * 8;
        a0 = ffma2(*reinterpret_cast<const ull*>(&xs[n][base]),
                   *reinterpret_cast<const ull*>(&pws[l][base]), a0);
        a1 = ffma2(*reinterpret_cast<const ull*>(&xs[n][base + 2]),
                   *reinterpret_cast<const ull*>(&pws[l][base + 2]), a1);
        a2 = ffma2(*reinterpret_cast<const ull*>(&xs[n][base + 4]),
                   *reinterpret_cast<const ull*>(&pws[l][base + 4]), a2);
        a3 = ffma2(*reinterpret_cast<const ull*>(&xs[n][base + 6]),
                   *reinterpret_cast<const ull*>(&pws[l][base + 6]), a3);
    }
    float acc = (hadd2(a0) + hadd2(a1)) + (hadd2(a2) + hadd2(a3)) + pb[l];

    __half zh = __float2half_rn(acc);
    g_zh[(size_t)(p0 + n) * LL + l] = zh;
    float az = __half2float(zh);
    zs[n][l] = acc;
    red[n][l] = az * az;
    __syncthreads();
    if (l == 0) {
        float s = 0.f;
#pragma unroll
        for (int j = 0; j < LL; j++) s += red[n][j];
        g_sqh[p0 + n] = s;
    }

    ull zp[8];
#pragma unroll
    for (int l2 = 0; l2 < 8; l2++) zp[l2] = *reinterpret_cast<const ull*>(&zs[n][l2 << 1]);

    float accum = 0.f;
#pragma unroll 4
    for (int i = 0; i < 16; i++) {
        const int f = l + 16 * i;
        ull d2 = 0ULL;
#pragma unroll
        for (int l2 = 0; l2 < 8; l2++) {
            ull wv = *reinterpret_cast<const ull*>(&w1s[f][l2 << 1]);
            d2 = ffma2(zp[l2], wv, d2);
        }
        float hv = hadd2(d2) + b1s[f];
        hv = fmaxf(hv, 0.f);
        accum = fmaf(hv, w2s[f], accum);
    }
#pragma unroll
    for (int o = 8; o > 0; o >>= 1) accum += __shfl_down_sync(0xffffffffu, accum, o, 16);
    if (l == 0) {
        float t = accum + b2[0];
        g_pi[p0 + n] = 1.0f / (1.0f + __expf(-t));
    }
}

// =====================================================================
// Kernel 2: symmetric K pass via HMMA Gram + wide fp16 ex2.
// Colsum from movmatrix fragments (2-level shfl chains only).
// =====================================================================
#define GPW 12
#define KPW 68
#define KTPH 136
#define O_ZN  0u
#define O_ZM  6144u
#define O_SQN 12288u
#define O_SQM 12800u
#define O_KT  13312u
#define O_KTT 48128u
#define O_RS  82944u
#define O_CS  83456u          // 8 x 132 floats
#define KK_SMEM 87680u

__global__ void __launch_bounds__(256, 2) k_K(void) {
    extern __shared__ __align__(16) unsigned char ks[];
    uint32_t* znW = reinterpret_cast<uint32_t*>(ks + O_ZN);
    uint32_t* zmW = reinterpret_cast<uint32_t*>(ks + O_ZM);
    float* sqnS = reinterpret_cast<float*>(ks + O_SQN);
    float* sqmS = reinterpret_cast<float*>(ks + O_SQM);
    uint32_t* ktW = reinterpret_cast<uint32_t*>(ks + O_KT);
    __half* ktT = reinterpret_cast<__half*>(ks + O_KTT);
    float* rsS = reinterpret_cast<float*>(ks + O_RS);
    float (*csS)[132] = reinterpret_cast<float(*)[132]>(ks + O_CS);

    const int tid = threadIdx.x;
    const int b = blockIdx.y;
    int p = blockIdx.x, ti = 0;
    while (p >= NT - ti) { p -= NT - ti; ti++; }
    const int tj = ti + p;
    const bool diag = (ti == tj);

    {
        const uint32_t* gn = reinterpret_cast<const uint32_t*>(
            g_zh + ((size_t)b * NN + ti * 128) * LL);
        const uint32_t* gm = reinterpret_cast<const uint32_t*>(
            g_zh + ((size_t)b * NN + tj * 128) * LL);
        for (int i = tid; i < 1024; i += 256) {
            znW[(i >> 3) * GPW + (i & 7)] = gn[i];
            zmW[(i >> 3) * GPW + (i & 7)] = gm[i];
        }
        const float* sqb = g_sqh + (size_t)b * NN;
        if (tid < 128) {
            sqnS[tid] = -NL2E * sqb[ti * 128 + tid];
            sqmS[tid] = -NL2E * sqb[tj * 128 + tid];
        }
    }
    __syncthreads();

    const int w = tid >> 5, lane = tid & 31;
    const int g = lane >> 2, q = lane & 3;
    const int r0 = w * 16 + g, r1 = r0 + 8;

    uint32_t af[4];
    af[0] = znW[r0 * GPW + q];
    af[1] = znW[r1 * GPW + q];
    af[2] = znW[r0 * GPW + q + 4];
    af[3] = znW[r1 * GPW + q + 4];

    float acc[16][4];
#pragma unroll
    for (int cf = 0; cf < 16; cf++) {
        acc[cf][0] = acc[cf][1] = acc[cf][2] = acc[cf][3] = 0.f;
        uint32_t bf[2];
        bf[0] = zmW[(cf * 8 + g) * GPW + q];
        bf[1] = zmW[(cf * 8 + g) * GPW + q + 4];
        mma16816(acc[cf], af, bf);
    }

    const float sqr0 = sqnS[r0], sqr1 = sqnS[r1];
    const float TWOL2E = 2.0f * NL2E;
    float rs0 = 0.f, rs1 = 0.f;
#pragma unroll
    for (int cf = 0; cf < 16; cf++) {
        const int c0 = cf * 8 + 2 * q;
        float2 sqc = *reinterpret_cast<const float2*>(&sqmS[c0]);
        float t00 = fminf(fmaf(TWOL2E, acc[cf][0], sqr0 + sqc.x), 0.f);
        float t01 = fminf(fmaf(TWOL2E, acc[cf][1], sqr0 + sqc.y), 0.f);
        float t10 = fminf(fmaf(TWOL2E, acc[cf][2], sqr1 + sqc.x), 0.f);
        float t11 = fminf(fmaf(TWOL2E, acc[cf][3], sqr1 + sqc.y), 0.f);
        __half2 e0 = __floats2half2_rn(t00, t01);
        __half2 e1 = __floats2half2_rn(t10, t11);
        uint32_t h0 = ex2_f16x2(*reinterpret_cast<uint32_t*>(&e0));
        uint32_t h1 = ex2_f16x2(*reinterpret_cast<uint32_t*>(&e1));

        rs0 += h2sum(h0);
        rs1 += h2sum(h1);

        ktW[r0 * KPW + (c0 >> 1)] = h0;
        ktW[r1 * KPW + (c0 >> 1)] = h1;

        if (!diag) {
            uint32_t h0t = movmat_t(h0);
            uint32_t h1t = movmat_t(h1);
            *reinterpret_cast<uint32_t*>(&ktT[(cf * 8 + g) * KTPH + w * 16 + 2 * q]) = h0t;
            *reinterpret_cast<uint32_t*>(&ktT[(cf * 8 + g) * KTPH + w * 16 + 8 + 2 * q]) = h1t;
            // colsum partial for column cf*8+g over rows w*16..w*16+15:
            // lane(g,q) transposed frags hold rows 2q,2q+1 (h0t) and 8+2q,8+2q+1 (h1t)
            float cp = h2sum(h0t) + h2sum(h1t);
            cp += __shfl_xor_sync(0xffffffffu, cp, 1);
            cp += __shfl_xor_sync(0xffffffffu, cp, 2);
            if (q == 0) csS[w][cf * 8 + g] = cp;
        }
    }
    rs0 += __shfl_xor_sync(0xffffffffu, rs0, 1);
    rs0 += __shfl_xor_sync(0xffffffffu, rs0, 2);
    rs1 += __shfl_xor_sync(0xffffffffu, rs1, 1);
    rs1 += __shfl_xor_sync(0xffffffffu, rs1, 2);
    if (q == 0) { rsS[r0] = rs0; rsS[r1] = rs1; }
    __syncthreads();

    if (tid < 128)
        g_qpart[((size_t)b * NT + tj) * NN + ti * 128 + tid] = rsS[tid];
    if (!diag && tid < 128) {
        float s = 0.f;
#pragma unroll
        for (int ww = 0; ww < 8; ww++) s += csS[ww][tid];
        g_qpart[((size_t)b * NT + ti) * NN + tj * 128 + tid] = s;
    }

    uint32_t* gK1 = reinterpret_cast<uint32_t*>(
        g_K + ((size_t)(b * NN + ti * 128)) * NN + tj * 128);
    for (int i = tid; i < 128 * 64; i += 256)
        gK1[(size_t)(i >> 6) * (NN / 2) + (i & 63)] = ktW[(i >> 6) * KPW + (i & 63)];
    if (!diag) {
        uint32_t* gK2 = reinterpret_cast<uint32_t*>(
            g_K + ((size_t)(b * NN + tj * 128)) * NN + ti * 128);
        const uint32_t* ktTW = reinterpret_cast<const uint32_t*>(ktT);
        for (int i = tid; i < 128 * 64; i += 256)
            gK2[(size_t)(i >> 6) * (NN / 2) + (i & 63)] = ktTW[(i >> 6) * KPW + (i & 63)];
    }
}

// =====================================================================
// Kernel 3: q = sum partials ; c = pi/q ; y[f][m] = c[m]*x[m][f] fp16.
// =====================================================================
__global__ void __launch_bounds__(256) k_y(const float* __restrict__ x) {
    __shared__ float cs[TK];
    __shared__ uint32_t yt[256][33];

    const int tid = threadIdx.x;
    const int mt = blockIdx.x, b = blockIdx.y;
    const float* xb = x + ((size_t)b * NN + mt * TK) * FF;

    if (tid < TK) {
        const int lm = mt * TK + tid;
        float q = 0.f;
#pragma unroll
        for (int s = 0; s < NT; s++) q += g_qpart[((size_t)b * NT + s) * NN + lm];
        float c = g_pi[b * NN + lm] / q;
        g_c[b * NN + lm] = c;
        cs[tid] = c;
    }
    __syncthreads();

    const int f = tid;
#pragma unroll 8
    for (int j = 0; j < 32; j++) {
        float y0 = cs[2 * j]     * __ldg(xb + (size_t)(2 * j) * FF + f);
        float y1 = cs[2 * j + 1] * __ldg(xb + (size_t)(2 * j + 1) * FF + f);
        __half2 hv = __floats2half2_rn(y0, y1);
        yt[f][j] = *reinterpret_cast<uint32_t*>(&hv);
    }
    __syncthreads();
    uint32_t* gY = reinterpret_cast<uint32_t*>(g_y + ((size_t)b * FF * NN + mt * TK));
    for (int i = tid; i < 256 * 32; i += 256)
        gY[(size_t)(i >> 5) * (NN / 2) + (i & 31)] = yt[i >> 5][i & 31];
}

// =====================================================================
// Kernel 4: HMMA GEMM, 4-stage cp.async, k-tile 32, hoisted LDSM batch.
// =====================================================================
#define KAPITCH 40
#define ABYTES3 (64 * 80)
#define BBYTES3 (256 * 80)
#define STAGE (ABYTES3 + BBYTES3)
#define NSTAGE 4
#define KTILES 64
#define OFF_C3  (NSTAGE * STAGE)
#define OFF_RS3 (OFF_C3 + 512)
#define OFF_SC3 (OFF_RS3 + 1024)
#define SMEM3   (OFF_SC3 + 256)

__global__ void __launch_bounds__(256, 2)
k_main(const float* __restrict__ x, float* __restrict__ out,
       const float* __restrict__ dtp) {
    extern __shared__ __align__(16) unsigned char sm[];
    const unsigned smb = smem_u32(sm);

    const int tid = threadIdx.x;
    const int nb = blockIdx.x, b = blockIdx.y;
    const int wid = tid >> 5, lane = tid & 31;
    const int g = lane >> 2, q = lane & 3;
    const int wm = wid & 1, wn = wid >> 1;

    const __half* Kg = g_K + (size_t)(b * NN + nb * 64) * NN;
    const __half* Yg = g_y + (size_t)b * FF * NN;
    const float* cg = g_c + (size_t)b * NN;

    auto fill = [&](int t, int st) {
        const unsigned aS = smb + st * STAGE;
        const unsigned bS = aS + ABYTES3;
        const __half* aG = Kg + t * 32;
        const __half* bG = Yg + t * 32;
        {
            const int i = tid;
            cp_async16s(aS + (i >> 2) * 80 + (i & 3) * 16,
                        aG + (size_t)(i >> 2) * NN + (i & 3) * 8);
        }
        for (int i = tid; i < 1024; i += 256)
            cp_async16s(bS + (i >> 2) * 80 + (i & 3) * 16,
                        bG + (size_t)(i >> 2) * NN + (i & 3) * 8);
        if (tid < 8)
            cp_async16s(smb + OFF_C3 + st * 128 + tid * 16, cg + t * 32 + tid * 4);
        cp_commit();
    };

    fill(0, 0);
    fill(1, 1);
    fill(2, 2);

    float acc[2][8][4];
#pragma unroll
    for (int mf = 0; mf < 2; mf++)
#pragma unroll
        for (int nf = 0; nf < 8; nf++)
#pragma unroll
            for (int k = 0; k < 4; k++) acc[mf][nf][k] = 0.f;
    float rs = 0.f;
    const int rn = tid & 63, qm = tid >> 6;

    const int a_row = wm * 32 + (lane & 15);
    const int a_kof = (lane >> 4) << 3;
    const int b_row = wn * 64 + (lane & 7) + ((lane >> 4) << 3);
    const int b_kof = ((lane >> 3) & 1) << 3;

    for (int t = 0; t < KTILES; t++) {
        const int st = t & 3;
        const int rem = KTILES - 1 - t;
        if (rem >= 2) cp_wait2(); else if (rem == 1) cp_wait1(); else cp_wait0();
        __syncthreads();
        if (t + 3 < KTILES) fill(t + 3, (t + 3) & 3);

        const unsigned KsA = smb + st * STAGE;
        const unsigned YsA = KsA + ABYTES3;
        const __half* Ks = reinterpret_cast<const __half*>(sm + st * STAGE);

        // --- hoist ALL fragment loads for this tile (both k-steps) ---
        uint32_t af[2][2][4];   // [ksI][mf][4]
        uint32_t bf[2][8][2];   // [ksI][nf][2]
#pragma unroll
        for (int ksI = 0; ksI < 2; ksI++) {
            const int k0 = ksI * 16;
#pragma unroll
            for (int mf = 0; mf < 2; mf++)
                ldsm4(af[ksI][mf], KsA + ((a_row + mf * 16) * KAPITCH + k0 + a_kof) * 2);
#pragma unroll
            for (int np = 0; np < 4; np++) {
                uint32_t r4[4];
                ldsm4(r4, YsA + ((b_row + np * 16) * KAPITCH + k0 + b_kof) * 2);
                bf[ksI][np * 2][0] = r4[0]; bf[ksI][np * 2][1] = r4[1];
                bf[ksI][np * 2 + 1][0] = r4[2]; bf[ksI][np * 2 + 1][1] = r4[3];
            }
        }

        // rowsum partial (independent of fragment stream)
        {
            const float* cP = reinterpret_cast<const float*>(sm + OFF_C3 + st * 128);
#pragma unroll
            for (int j = 0; j < 4; j++) {
                __half2 hv = *reinterpret_cast<const __half2*>(Ks + rn * KAPITCH + qm * 8 + 2 * j);
                float2 fv = __half22float2(hv);
                rs = fmaf(fv.x, cP[qm * 8 + 2 * j], rs);
                rs = fmaf(fv.y, cP[qm * 8 + 2 * j + 1], rs);
            }
        }

#pragma unroll
        for (int ksI = 0; ksI < 2; ksI++)
#pragma unroll
            for (int mf = 0; mf < 2; mf++)
#pragma unroll
                for (int nf = 0; nf < 8; nf++)
                    mma16816(acc[mf][nf], af[ksI][mf], bf[ksI][nf]);
    }

    __syncthreads();
    reinterpret_cast<float*>(sm + OFF_RS3)[rn * 4 + qm] = rs;
    __syncthreads();
    const float dtv = dtp[0];
    if (tid < 64) {
        const float* rp = reinterpret_cast<const float*>(sm + OFF_RS3) + tid * 4;
        float row = rp[0] + rp[1] + rp[2] + rp[3] + 1e-5f;
        reinterpret_cast<float*>(sm + OFF_SC3)[tid] = (dtv / EPSV) / row;
    }
    __syncthreads();

    const float omdt = 1.0f - dtv;
    const float* scS = reinterpret_cast<const float*>(sm + OFF_SC3);
#pragma unroll
    for (int mf = 0; mf < 2; mf++) {
        const int lr = wm * 32 + mf * 16 + g;
        const float sc1 = scS[lr], sc2 = scS[lr + 8];
        const size_t r1 = (size_t)(b * NN + nb * 64 + lr) * FF;
        const size_t r2 = r1 + (size_t)8 * FF;
#pragma unroll
        for (int nf = 0; nf < 8; nf++) {
            const int col = wn * 64 + nf * 8 + 2 * q;
            float2 x1 = *reinterpret_cast<const float2*>(x + r1 + col);
            float2 x2 = *reinterpret_cast<const float2*>(x + r2 + col);
            float2 o1, o2;
            o1.x = omdt * x1.x + sc1 * acc[mf][nf][0];
            o1.y = omdt * x1.y + sc1 * acc[mf][nf][1];
            o2.x = omdt * x2.x + sc2 * acc[mf][nf][2];
            o2.y = omdt * x2.y + sc2 * acc[mf][nf][3];
            *reinterpret_cast<float2*>(out + r1 + col) = o1;
            *reinterpret_cast<float2*>(out + r2 + col) = o2;
        }
    }
}

// =====================================================================
// launch
// =====================================================================
extern "C" void kernel_launch(void* const* d_in, const int* in_sizes, int n_in,
                              void* d_out, int out_size) {
    const float* x  = (const float*)d_in[0];
    const float* pw = (const float*)d_in[1];
    const float* pb = (const float*)d_in[2];
    const float* w1 = (const float*)d_in[3];
    const float* b1 = (const float*)d_in[4];
    const float* w2 = (const float*)d_in[5];
    const float* b2 = (const float*)d_in[6];
    const float* dt = (const float*)d_in[7];
    float* out = (float*)d_out;

    (void)in_sizes; (void)n_in; (void)out_size;

    const int npts = BB * NN;

    k_zpi<<<npts / 16, 256>>>(x, pw, pb, w1, b1, w2, b2);

    cudaFuncSetAttribute(k_K, cudaFuncAttributeMaxDynamicSharedMemorySize, (int)KK_SMEM);
    k_K<<<dim3(NPAIRS, BB), 256, KK_SMEM>>>();

    k_y<<<dim3(MTILES, BB), 256>>>(x);

    cudaFuncSetAttribute(k_main, cudaFuncAttributeMaxDynamicSharedMemorySize, (int)SMEM3);
    k_main<<<dim3(NN / 64, BB), 256, SMEM3>>>(x, out, dt);
}

// round 10
// speedup vs baseline: 1.0124x; 1.0124x over previous
#include <cuda_runtime.h>
#include <cuda_fp16.h>
#include <cstdint>

// Problem constants (TMDLayer): B=8, N=2048, F=256, L=16, EPS=0.25
#define BB 8
#define NN 2048
#define FF 256
#define LL 16
#define EPSV 0.25f
#define YT 64          // k_y m-tiles of 32
#define YTK 32
#define NT 16          // k_K tiles of 128
#define NPAIRS 136
#define NL2E 1.4426950408889634f

typedef unsigned long long ull;

// ---------------- device scratch ----------------
__device__ __half g_zh[BB * NN * LL];
__device__ float g_sqh[BB * NN];
__device__ float g_pi[BB * NN];
__device__ float g_c[BB * NN];
__device__ float g_qpart[(size_t)BB * NT * NN];
__device__ __align__(128) __half g_K[(size_t)BB * NN * NN];   // [b][n][m]
__device__ __align__(128) __half g_y[(size_t)BB * FF * NN];   // [b][f][m]

// ---------------- helpers ----------------
__device__ __forceinline__ void grid_dep_wait() {
    asm volatile("griddepcontrol.wait;" ::: "memory");
}
__device__ __forceinline__ unsigned smem_u32(const void* p) {
    unsigned a;
    asm("{ .reg .u64 t; cvta.to.shared.u64 t, %1; cvt.u32.u64 %0, t; }" : "=r"(a) : "l"(p));
    return a;
}
__device__ __forceinline__ void cp_async16s(unsigned dst, const void* src) {
    asm volatile("cp.async.cg.shared.global [%0], [%1], 16;\n" :: "r"(dst), "l"(src));
}
__device__ __forceinline__ void cp_commit() { asm volatile("cp.async.commit_group;\n"); }
__device__ __forceinline__ void cp_wait0() { asm volatile("cp.async.wait_group 0;\n"); }
__device__ __forceinline__ void cp_wait1() { asm volatile("cp.async.wait_group 1;\n"); }
__device__ __forceinline__ void cp_wait2() { asm volatile("cp.async.wait_group 2;\n"); }

__device__ __forceinline__ ull ffma2(ull a, ull b, ull c) {
    ull d;
    asm("fma.rn.f32x2 %0, %1, %2, %3;" : "=l"(d) : "l"(a), "l"(b), "l"(c));
    return d;
}
union F2U { ull u; float2 f; };
__device__ __forceinline__ float hadd2(ull v) { F2U t; t.u = v; return t.f.x + t.f.y; }

__device__ __forceinline__ void mma16816(float* d, const uint32_t* a, const uint32_t* b) {
    asm volatile(
        "mma.sync.aligned.m16n8k16.row.col.f32.f16.f16.f32 "
        "{%0,%1,%2,%3}, {%4,%5,%6,%7}, {%8,%9}, {%0,%1,%2,%3};"
        : "+f"(d[0]), "+f"(d[1]), "+f"(d[2]), "+f"(d[3])
        : "r"(a[0]), "r"(a[1]), "r"(a[2]), "r"(a[3]), "r"(b[0]), "r"(b[1]));
}
__device__ __forceinline__ void ldsm4(uint32_t* r, unsigned addr) {
    asm volatile("ldmatrix.sync.aligned.m8n8.x4.shared.b16 {%0,%1,%2,%3}, [%4];"
        : "=r"(r[0]), "=r"(r[1]), "=r"(r[2]), "=r"(r[3]) : "r"(addr));
}
__device__ __forceinline__ uint32_t ex2_f16x2(uint32_t a) {
    uint32_t d;
    asm("ex2.approx.f16x2 %0, %1;" : "=r"(d) : "r"(a));
    return d;
}
__device__ __forceinline__ uint32_t movmat_t(uint32_t a) {
    uint32_t d;
    asm("movmatrix.sync.aligned.m8n8.trans.b16 %0, %1;" : "=r"(d) : "r"(a));
    return d;
}
__device__ __forceinline__ float h2sum(uint32_t h) {
    __half2 v = *reinterpret_cast<__half2*>(&h);
    float2 f = __half22float2(v);
    return f.x + f.y;
}

// =====================================================================
// Kernel 1 (fused): z, zh, sqh, pi.  proj dot LDS.128 + 4-way accum.
// =====================================================================
__global__ void __launch_bounds__(256) k_zpi(const float* __restrict__ x,
                                             const float* __restrict__ pw,
                                             const float* __restrict__ pb,
                                             const float* __restrict__ w1,
                                             const float* __restrict__ b1,
                                             const float* __restrict__ w2,
                                             const float* __restrict__ b2) {
    __shared__ __align__(16) float xs[16][260];
    __shared__ __align__(16) float pws[16][260];
    __shared__ __align__(16) float zs[16][18];
    __shared__ float red[16][17];
    __shared__ __align__(16) float w1s[256][18];
    __shared__ float b1s[256];
    __shared__ float w2s[256];

    const int tid = threadIdx.x;
    const int p0 = blockIdx.x * 16;
    const float* xbase = x + (size_t)p0 * FF;

    for (int i = tid; i < 16 * 64; i += 256) {
        int r = i >> 6, c = (i & 63) << 2;
        float4 v = *reinterpret_cast<const float4*>(xbase + r * FF + c);
        *reinterpret_cast<float4*>(&xs[r][c]) = v;
    }
    for (int i = tid; i < LL * FF; i += 256) pws[i >> 8][i & 255] = pw[i];
    for (int i = tid; i < FF * LL; i += 256) w1s[i >> 4][i & 15] = w1[i];
    b1s[tid] = b1[tid];
    w2s[tid] = w2[tid];
    __syncthreads();

    const int n = tid >> 4;
    const int l = tid & 15;
    ull a0 = 0ULL, a1 = 0ULL, a2 = 0ULL, a3 = 0ULL;
#pragma unroll 8
    for (int f8 = 0; f8 < FF / 8; f8++) {
        const int base = f8 * 8;
        ulonglong2 xv0 = *reinterpret_cast<const ulonglong2*>(&xs[n][base]);
        ulonglong2 wv0 = *reinterpret_cast<const ulonglong2*>(&pws[l][base]);
        ulonglong2 xv1 = *reinterpret_cast<const ulonglong2*>(&xs[n][base + 4]);
        ulonglong2 wv1 = *reinterpret_cast<const ulonglong2*>(&pws[l][base + 4]);
        a0 = ffma2(xv0.x, wv0.x, a0);
        a1 = ffma2(xv0.y, wv0.y, a1);
        a2 = ffma2(xv1.x, wv1.x, a2);
        a3 = ffma2(xv1.y, wv1.y, a3);
    }
    float acc = (hadd2(a0) + hadd2(a1)) + (hadd2(a2) + hadd2(a3)) + pb[l];

    __half zh = __float2half_rn(acc);
    g_zh[(size_t)(p0 + n) * LL + l] = zh;
    float az = __half2float(zh);
    zs[n][l] = acc;
    red[n][l] = az * az;
    __syncthreads();
    if (l == 0) {
        float s = 0.f;
#pragma unroll
        for (int j = 0; j < LL; j++) s += red[n][j];
        g_sqh[p0 + n] = s;
    }

    ull zp[8];
#pragma unroll
    for (int l2 = 0; l2 < 8; l2++) zp[l2] = *reinterpret_cast<const ull*>(&zs[n][l2 << 1]);

    float accum = 0.f;
#pragma unroll 4
    for (int i = 0; i < 16; i++) {
        const int f = l + 16 * i;
        ull d2 = 0ULL;
#pragma unroll
        for (int l2 = 0; l2 < 8; l2++) {
            ull wv = *reinterpret_cast<const ull*>(&w1s[f][l2 << 1]);
            d2 = ffma2(zp[l2], wv, d2);
        }
        float hv = hadd2(d2) + b1s[f];
        hv = fmaxf(hv, 0.f);
        accum = fmaf(hv, w2s[f], accum);
    }
#pragma unroll
    for (int o = 8; o > 0; o >>= 1) accum += __shfl_down_sync(0xffffffffu, accum, o, 16);
    if (l == 0) {
        float t = accum + b2[0];
        g_pi[p0 + n] = 1.0f / (1.0f + __expf(-t));
    }
}

// =====================================================================
// Kernel 2: symmetric K pass via HMMA Gram + wide fp16 ex2.
// 128-bit writeout. PDL-dependent on k_zpi.
// =====================================================================
#define GPW 12
#define KPW 68
#define KTPH 136
#define O_ZN  0u
#define O_ZM  6144u
#define O_SQN 12288u
#define O_SQM 12800u
#define O_KT  13312u
#define O_KTT 48128u
#define O_RS  82944u
#define O_CS  83456u
#define KK_SMEM 87680u

__global__ void __launch_bounds__(256, 2) k_K(void) {
    extern __shared__ __align__(16) unsigned char ks[];
    uint32_t* znW = reinterpret_cast<uint32_t*>(ks + O_ZN);
    uint32_t* zmW = reinterpret_cast<uint32_t*>(ks + O_ZM);
    float* sqnS = reinterpret_cast<float*>(ks + O_SQN);
    float* sqmS = reinterpret_cast<float*>(ks + O_SQM);
    uint32_t* ktW = reinterpret_cast<uint32_t*>(ks + O_KT);
    __half* ktT = reinterpret_cast<__half*>(ks + O_KTT);
    float* rsS = reinterpret_cast<float*>(ks + O_RS);
    float (*csS)[132] = reinterpret_cast<float(*)[132]>(ks + O_CS);

    const int tid = threadIdx.x;
    const int b = blockIdx.y;
    int p = blockIdx.x, ti = 0;
    while (p >= NT - ti) { p -= NT - ti; ti++; }
    const int tj = ti + p;
    const bool diag = (ti == tj);

    grid_dep_wait();

    {
        const uint32_t* gn = reinterpret_cast<const uint32_t*>(
            g_zh + ((size_t)b * NN + ti * 128) * LL);
        const uint32_t* gm = reinterpret_cast<const uint32_t*>(
            g_zh + ((size_t)b * NN + tj * 128) * LL);
        for (int i = tid; i < 1024; i += 256) {
            znW[(i >> 3) * GPW + (i & 7)] = gn[i];
            zmW[(i >> 3) * GPW + (i & 7)] = gm[i];
        }
        const float* sqb = g_sqh + (size_t)b * NN;
        if (tid < 128) {
            sqnS[tid] = -NL2E * sqb[ti * 128 + tid];
            sqmS[tid] = -NL2E * sqb[tj * 128 + tid];
        }
    }
    __syncthreads();

    const int w = tid >> 5, lane = tid & 31;
    const int g = lane >> 2, q = lane & 3;
    const int r0 = w * 16 + g, r1 = r0 + 8;

    uint32_t af[4];
    af[0] = znW[r0 * GPW + q];
    af[1] = znW[r1 * GPW + q];
    af[2] = znW[r0 * GPW + q + 4];
    af[3] = znW[r1 * GPW + q + 4];

    float acc[16][4];
#pragma unroll
    for (int cf = 0; cf < 16; cf++) {
        acc[cf][0] = acc[cf][1] = acc[cf][2] = acc[cf][3] = 0.f;
        uint32_t bf[2];
        bf[0] = zmW[(cf * 8 + g) * GPW + q];
        bf[1] = zmW[(cf * 8 + g) * GPW + q + 4];
        mma16816(acc[cf], af, bf);
    }

    const float sqr0 = sqnS[r0], sqr1 = sqnS[r1];
    const float TWOL2E = 2.0f * NL2E;
    float rs0 = 0.f, rs1 = 0.f;
#pragma unroll
    for (int cf = 0; cf < 16; cf++) {
        const int c0 = cf * 8 + 2 * q;
        float2 sqc = *reinterpret_cast<const float2*>(&sqmS[c0]);
        float t00 = fminf(fmaf(TWOL2E, acc[cf][0], sqr0 + sqc.x), 0.f);
        float t01 = fminf(fmaf(TWOL2E, acc[cf][1], sqr0 + sqc.y), 0.f);
        float t10 = fminf(fmaf(TWOL2E, acc[cf][2], sqr1 + sqc.x), 0.f);
        float t11 = fminf(fmaf(TWOL2E, acc[cf][3], sqr1 + sqc.y), 0.f);
        __half2 e0 = __floats2half2_rn(t00, t01);
        __half2 e1 = __floats2half2_rn(t10, t11);
        uint32_t h0 = ex2_f16x2(*reinterpret_cast<uint32_t*>(&e0));
        uint32_t h1 = ex2_f16x2(*reinterpret_cast<uint32_t*>(&e1));

        rs0 += h2sum(h0);
        rs1 += h2sum(h1);

        ktW[r0 * KPW + (c0 >> 1)] = h0;
        ktW[r1 * KPW + (c0 >> 1)] = h1;

        if (!diag) {
            uint32_t h0t = movmat_t(h0);
            uint32_t h1t = movmat_t(h1);
            *reinterpret_cast<uint32_t*>(&ktT[(cf * 8 + g) * KTPH + w * 16 + 2 * q]) = h0t;
            *reinterpret_cast<uint32_t*>(&ktT[(cf * 8 + g) * KTPH + w * 16 + 8 + 2 * q]) = h1t;
            float cp = h2sum(h0t) + h2sum(h1t);
            cp += __shfl_xor_sync(0xffffffffu, cp, 1);
            cp += __shfl_xor_sync(0xffffffffu, cp, 2);
            if (q == 0) csS[w][cf * 8 + g] = cp;
        }
    }
    rs0 += __shfl_xor_sync(0xffffffffu, rs0, 1);
    rs0 += __shfl_xor_sync(0xffffffffu, rs0, 2);
    rs1 += __shfl_xor_sync(0xffffffffu, rs1, 1);
    rs1 += __shfl_xor_sync(0xffffffffu, rs1, 2);
    if (q == 0) { rsS[r0] = rs0; rsS[r1] = rs1; }
    __syncthreads();

    if (tid < 128)
        g_qpart[((size_t)b * NT + tj) * NN + ti * 128 + tid] = rsS[tid];
    if (!diag && tid < 128) {
        float s = 0.f;
#pragma unroll
        for (int ww = 0; ww < 8; ww++) s += csS[ww][tid];
        g_qpart[((size_t)b * NT + ti) * NN + tj * 128 + tid] = s;
    }

    // 128-bit writeout: 128 rows x 16 float4 per matrix
    {
        float4* gK1 = reinterpret_cast<float4*>(
            g_K + ((size_t)(b * NN + ti * 128)) * NN + tj * 128);
        for (int i = tid; i < 2048; i += 256) {
            const int r = i >> 4, j = i & 15;
            gK1[(size_t)r * (NN / 8) + j] =
                *reinterpret_cast<const float4*>(ktW + r * KPW + 4 * j);
        }
        if (!diag) {
            float4* gK2 = reinterpret_cast<float4*>(
                g_K + ((size_t)(b * NN + tj * 128)) * NN + ti * 128);
            const uint32_t* ktTW = reinterpret_cast<const uint32_t*>(ktT);
            for (int i = tid; i < 2048; i += 256) {
                const int r = i >> 4, j = i & 15;
                gK2[(size_t)r * (NN / 8) + j] =
                    *reinterpret_cast<const float4*>(ktTW + r * KPW + 4 * j);
            }
        }
    }
}

// =====================================================================
// Kernel 3: q = sum partials ; c = pi/q ; y[f][m] = c[m]*x[m][f] fp16.
// m-tile 32, 512 CTAs. PDL-dependent on k_K.
// =====================================================================
__global__ void __launch_bounds__(256) k_y(const float* __restrict__ x) {
    __shared__ float cs[YTK];
    __shared__ uint32_t yt[256][17];

    const int tid = threadIdx.x;
    const int mt = blockIdx.x, b = blockIdx.y;

    grid_dep_wait();

    const float* xb = x + ((size_t)b * NN + mt * YTK) * FF;

    if (tid < YTK) {
        const int lm = mt * YTK + tid;
        float q = 0.f;
#pragma unroll
        for (int s = 0; s < NT; s++) q += g_qpart[((size_t)b * NT + s) * NN + lm];
        float c = g_pi[b * NN + lm] / q;
        g_c[b * NN + lm] = c;
        cs[tid] = c;
    }
    __syncthreads();

    const int f = tid;
#pragma unroll 8
    for (int j = 0; j < 16; j++) {
        float y0 = cs[2 * j]     * __ldg(xb + (size_t)(2 * j) * FF + f);
        float y1 = cs[2 * j + 1] * __ldg(xb + (size_t)(2 * j + 1) * FF + f);
        __half2 hv = __floats2half2_rn(y0, y1);
        yt[f][j] = *reinterpret_cast<uint32_t*>(&hv);
    }
    __syncthreads();
    uint32_t* gY = reinterpret_cast<uint32_t*>(g_y + ((size_t)b * FF * NN + mt * YTK));
    for (int i = tid; i < 256 * 16; i += 256)
        gY[(size_t)(i >> 4) * (NN / 2) + (i & 15)] = yt[i >> 4][i & 15];
}

// =====================================================================
// Kernel 4: HMMA GEMM, 4-stage cp.async, k-tile 32. PDL-dependent on k_y.
// =====================================================================
#define KAPITCH 40
#define ABYTES3 (64 * 80)
#define BBYTES3 (256 * 80)
#define STAGE (ABYTES3 + BBYTES3)
#define NSTAGE 4
#define KTILES 64
#define OFF_C3  (NSTAGE * STAGE)
#define OFF_RS3 (OFF_C3 + 512)
#define OFF_SC3 (OFF_RS3 + 1024)
#define SMEM3   (OFF_SC3 + 256)

__global__ void __launch_bounds__(256, 2)
k_main(const float* __restrict__ x, float* __restrict__ out,
       const float* __restrict__ dtp) {
    extern __shared__ __align__(16) unsigned char sm[];
    const unsigned smb = smem_u32(sm);

    const int tid = threadIdx.x;
    const int nb = blockIdx.x, b = blockIdx.y;
    const int wid = tid >> 5, lane = tid & 31;
    const int g = lane >> 2, q = lane & 3;
    const int wm = wid & 1, wn = wid >> 1;

    const __half* Kg = g_K + (size_t)(b * NN + nb * 64) * NN;
    const __half* Yg = g_y + (size_t)b * FF * NN;
    const float* cg = g_c + (size_t)b * NN;

    grid_dep_wait();

    auto fill = [&](int t, int st) {
        const unsigned aS = smb + st * STAGE;
        const unsigned bS = aS + ABYTES3;
        const __half* aG = Kg + t * 32;
        const __half* bG = Yg + t * 32;
        {
            const int i = tid;
            cp_async16s(aS + (i >> 2) * 80 + (i & 3) * 16,
                        aG + (size_t)(i >> 2) * NN + (i & 3) * 8);
        }
        for (int i = tid; i < 1024; i += 256)
            cp_async16s(bS + (i >> 2) * 80 + (i & 3) * 16,
                        bG + (size_t)(i >> 2) * NN + (i & 3) * 8);
        if (tid < 8)
            cp_async16s(smb + OFF_C3 + st * 128 + tid * 16, cg + t * 32 + tid * 4);
        cp_commit();
    };

    fill(0, 0);
    fill(1, 1);
    fill(2, 2);

    float acc[2][8][4];
#pragma unroll
    for (int mf = 0; mf < 2; mf++)
#pragma unroll
        for (int nf = 0; nf < 8; nf++)
#pragma unroll
            for (int k = 0; k < 4; k++) acc[mf][nf][k] = 0.f;
    float rs = 0.f;
    const int rn = tid & 63, qm = tid >> 6;

    const int a_row = wm * 32 + (lane & 15);
    const int a_kof = (lane >> 4) << 3;
    const int b_row = wn * 64 + (lane & 7) + ((lane >> 4) << 3);
    const int b_kof = ((lane >> 3) & 1) << 3;

    for (int t = 0; t < KTILES; t++) {
        const int st = t & 3;
        const int rem = KTILES - 1 - t;
        if (rem >= 2) cp_wait2(); else if (rem == 1) cp_wait1(); else cp_wait0();
        __syncthreads();
        if (t + 3 < KTILES) fill(t + 3, (t + 3) & 3);

        const unsigned KsA = smb + st * STAGE;
        const unsigned YsA = KsA + ABYTES3;
        const __half* Ks = reinterpret_cast<const __half*>(sm + st * STAGE);

        uint32_t af[2][2][4];
        uint32_t bf[2][8][2];
#pragma unroll
        for (int ksI = 0; ksI < 2; ksI++) {
            const int k0 = ksI * 16;
#pragma unroll
            for (int mf = 0; mf < 2; mf++)
                ldsm4(af[ksI][mf], KsA + ((a_row + mf * 16) * KAPITCH + k0 + a_kof) * 2);
#pragma unroll
            for (int np = 0; np < 4; np++) {
                uint32_t r4[4];
                ldsm4(r4, YsA + ((b_row + np * 16) * KAPITCH + k0 + b_kof) * 2);
                bf[ksI][np * 2][0] = r4[0]; bf[ksI][np * 2][1] = r4[1];
                bf[ksI][np * 2 + 1][0] = r4[2]; bf[ksI][np * 2 + 1][1] = r4[3];
            }
        }

        {
            const float* cP = reinterpret_cast<const float*>(sm + OFF_C3 + st * 128);
#pragma unroll
            for (int j = 0; j < 4; j++) {
                __half2 hv = *reinterpret_cast<const __half2*>(Ks + rn * KAPITCH + qm * 8 + 2 * j);
                float2 fv = __half22float2(hv);
                rs = fmaf(fv.x, cP[qm * 8 + 2 * j], rs);
                rs = fmaf(fv.y, cP[qm * 8 + 2 * j + 1], rs);
            }
        }

#pragma unroll
        for (int ksI = 0; ksI < 2; ksI++)
#pragma unroll
            for (int mf = 0; mf < 2; mf++)
#pragma unroll
                for (int nf = 0; nf < 8; nf++)
                    mma16816(acc[mf][nf], af[ksI][mf], bf[ksI][nf]);
    }

    __syncthreads();
    reinterpret_cast<float*>(sm + OFF_RS3)[rn * 4 + qm] = rs;
    __syncthreads();
    const float dtv = dtp[0];
    if (tid < 64) {
        const float* rp = reinterpret_cast<const float*>(sm + OFF_RS3) + tid * 4;
        float row = rp[0] + rp[1] + rp[2] + rp[3] + 1e-5f;
        reinterpret_cast<float*>(sm + OFF_SC3)[tid] = (dtv / EPSV) / row;
    }
    __syncthreads();

    const float omdt = 1.0f - dtv;
    const float* scS = reinterpret_cast<const float*>(sm + OFF_SC3);
#pragma unroll
    for (int mf = 0; mf < 2; mf++) {
        const int lr = wm * 32 + mf * 16 + g;
        const float sc1 = scS[lr], sc2 = scS[lr + 8];
        const size_t r1 = (size_t)(b * NN + nb * 64 + lr) * FF;
        const size_t r2 = r1 + (size_t)8 * FF;
#pragma unroll
        for (int nf = 0; nf < 8; nf++) {
            const int col = wn * 64 + nf * 8 + 2 * q;
            float2 x1 = *reinterpret_cast<const float2*>(x + r1 + col);
            float2 x2 = *reinterpret_cast<const float2*>(x + r2 + col);
            float2 o1, o2;
            o1.x = omdt * x1.x + sc1 * acc[mf][nf][0];
            o1.y = omdt * x1.y + sc1 * acc[mf][nf][1];
            o2.x = omdt * x2.x + sc2 * acc[mf][nf][2];
            o2.y = omdt * x2.y + sc2 * acc[mf][nf][3];
            *reinterpret_cast<float2*>(out + r1 + col) = o1;
            *reinterpret_cast<float2*>(out + r2 + col) = o2;
        }
    }
}

// =====================================================================
// launch — PDL chain: k_zpi -> k_K -> k_y -> k_main
// =====================================================================
extern "C" void kernel_launch(void* const* d_in, const int* in_sizes, int n_in,
                              void* d_out, int out_size) {
    const float* x  = (const float*)d_in[0];
    const float* pw = (const float*)d_in[1];
    const float* pb = (const float*)d_in[2];
    const float* w1 = (const float*)d_in[3];
    const float* b1 = (const float*)d_in[4];
    const float* w2 = (const float*)d_in[5];
    const float* b2 = (const float*)d_in[6];
    const float* dt = (const float*)d_in[7];
    float* out = (float*)d_out;

    (void)in_sizes; (void)n_in; (void)out_size;

    const int npts = BB * NN;

    cudaFuncSetAttribute(k_K, cudaFuncAttributeMaxDynamicSharedMemorySize, (int)KK_SMEM);
    cudaFuncSetAttribute(k_main, cudaFuncAttributeMaxDynamicSharedMemorySize, (int)SMEM3);

    k_zpi<<<npts / 16, 256>>>(x, pw, pb, w1, b1, w2, b2);

    cudaLaunchAttribute at[1];
    at[0].id = cudaLaunchAttributeProgrammaticStreamSerialization;
    at[0].val.programmaticStreamSerializationAllowed = 1;

    cudaLaunchConfig_t cfg;
    memset(&cfg, 0, sizeof(cfg));
    cfg.blockDim = dim3(256, 1, 1);
    cfg.attrs = at;
    cfg.numAttrs = 1;
    cfg.stream = 0;

    cfg.gridDim = dim3(NPAIRS, BB, 1);
    cfg.dynamicSmemBytes = KK_SMEM;
    cudaLaunchKernelEx(&cfg, k_K);

    cfg.gridDim = dim3(YT, BB, 1);
    cfg.dynamicSmemBytes = 0;
    cudaLaunchKernelEx(&cfg, k_y, x);

    cfg.gridDim = dim3(NN / 64, BB, 1);
    cfg.dynamicSmemBytes = SMEM3;
    cudaLaunchKernelEx(&cfg, k_main, x, out, dt);
}